// round 15
// baseline (speedup 1.0000x reference)
#include <cuda_runtime.h>
#include <cuda_fp16.h>
#include <cstdint>

#define DEV_INLINE __device__ __forceinline__

constexpr int L_   = 100;
constexpr int B_   = 32;
constexpr int E_   = 512;
constexpr int F_   = 256;
constexpr int M_   = 128;
constexpr int D_   = 258;
constexpr int NPAIR = L_ * L_;                 // 10000
constexpr int NTILE = (NPAIR + 127) / 128;     // 79
constexpr int NJOB  = NTILE * B_;              // 2528
constexpr int NROW  = B_ * L_;                 // 3200 = 25 * 128
constexpr int RTILE = 25;

// packed conv-weight fragment array bases (uint4 units)
constexpr int CB0 = 0;
constexpr int CB1 = 98304;
constexpr int CB2 = 147456;
constexpr int CB3 = 196608;
constexpr int CWP_TOTAL = 245760;

// ---------------- scratch (device globals; no allocation allowed) ----------------
__device__ float g_act1[NROW * F_];
__device__ float g_act2[NROW * F_];
__device__ float g_csum [4][F_][32];
__device__ float g_csum2[4][F_][32];
__device__ float g_A[B_ * L_ * M_];
__device__ float g_C[B_ * L_ * M_];
__device__ float g_part[B_ * NTILE * M_];
__device__ __align__(16) uint4 g_wpack2[3][128 * 32];   // pairwise weights
__device__ __align__(16) uint4 g_cwp[CWP_TOTAL];        // conv weights (fragments)

DEV_INLINE float lrelu(float z) { return fmaxf(z, 0.f) + 0.1f * fminf(z, 0.f); }

DEV_INLINE uint32_t pack_h2(float x0, float x1) {
    __half2 h = __floats2half2_rn(x0, x1);
    return *reinterpret_cast<uint32_t*>(&h);
}

DEV_INLINE void split2h(float x0, float x1, uint32_t& hi, uint32_t& lo) {
    __half h0 = __float2half_rn(x0);
    __half h1 = __float2half_rn(x1);
    float r0 = x0 - __half2float(h0);
    float r1 = x1 - __half2float(h1);
    __half2 hh = __halves2half2(h0, h1);
    hi = *reinterpret_cast<uint32_t*>(&hh);
    lo = pack_h2(r0, r1);
}

DEV_INLINE void mma16816_f16(float c[4], const uint32_t a[4], uint32_t b0, uint32_t b1) {
    asm volatile(
        "mma.sync.aligned.m16n8k16.row.col.f32.f16.f16.f32 "
        "{%0,%1,%2,%3}, {%4,%5,%6,%7}, {%8,%9}, {%0,%1,%2,%3};"
        : "+f"(c[0]), "+f"(c[1]), "+f"(c[2]), "+f"(c[3])
        : "r"(a[0]), "r"(a[1]), "r"(a[2]), "r"(a[3]), "r"(b0), "r"(b1));
}

// =================================================================================
// One-time conv weight pack (fp16 hi/lo fragment uint4s; layout matches conv MMA).
// =================================================================================
__global__ void __launch_bounds__(256) pack_conv(
    const float* __restrict__ cw1, const float* __restrict__ cw2,
    const float* __restrict__ cw3, const float* __restrict__ cw4)
{
    int idx = blockIdx.x * 256 + threadIdx.x;
    if (idx >= CWP_TOTAL) return;
    const float* cw; int EIN, NKC, rem;
    if (idx < CB1)      { rem = idx;       cw = cw1; EIN = 512; NKC = 4; }
    else if (idx < CB2) { rem = idx - CB1; cw = cw2; EIN = 256; NKC = 2; }
    else if (idx < CB3) { rem = idx - CB2; cw = cw3; EIN = 256; NKC = 2; }
    else                { rem = idx - CB3; cw = cw4; EIN = 256; NKC = 2; }
    int per_by = 3 * NKC * 2048;
    int by = rem / per_by;
    int r2 = rem - by * per_by;
    int s  = r2 / (NKC * 2048);
    int r3 = r2 - s * (NKC * 2048);
    int kc = r3 >> 11;
    int id = r3 & 2047;
    int n  = id >> 5;
    int j  = id & 31;
    int jj = j ^ ((n & 1) * 4);
    int e0 = 128 * kc + 16 * (jj >> 2) + 2 * (jj & 3);
    const float* wp = cw + ((size_t)(by * 64 + n) * EIN + e0) * 3 + s;
    float v0 = wp[0], v1 = wp[3], v2 = wp[24], v3 = wp[27];
    uint32_t h01, l01, h23, l23;
    split2h(v0, v1, h01, l01);
    split2h(v2, v3, h23, l23);
    g_cwp[idx] = make_uint4(h01, h23, l01, l23);
}

// =================================================================================
// Conv layer 1 (EIN=512, input x in (L,B,E)) — R13/R14 phase-staged version.
// =================================================================================
constexpr int CSMEM1 = 32768 + 4096 + 4096;

__global__ void __launch_bounds__(256, 2) conv1_mma(
    const float* __restrict__ x_ext,
    const float* __restrict__ cb)
{
    constexpr int EIN = 512;
    constexpr int NKC = 4;
    extern __shared__ char smraw[];
    uint4*  smW   = (uint4*)smraw;
    float*  s_sum = (float*)(smraw + 32768 + 4096);
    float*  s_sq  = s_sum + 512;

    const int tile = blockIdx.x;
    const int by   = blockIdx.y;
    const int f0   = by * 64;
    const int row0 = tile * 128;
    const int tid  = threadIdx.x;
    const int w    = tid >> 5;
    const int lane = tid & 31;
    const int g    = lane >> 2;
    const int t    = lane & 3;

    const int r0 = row0 + 16 * w + g;
    const int r1 = r0 + 8;
    const int b0r = r0 / 100, l0r = r0 - b0r * 100;
    const int b1r = r1 / 100, l1r = r1 - b1r * 100;

    float acc[8][4];
#pragma unroll
    for (int nt = 0; nt < 8; nt++)
#pragma unroll
        for (int q = 0; q < 4; q++) acc[nt][q] = 0.f;

#pragma unroll 1
    for (int s = 0; s < 3; s++) {
        const bool m0 = (unsigned)(l0r + s - 1) < 100u;
        const bool m1 = (unsigned)(l1r + s - 1) < 100u;
        const float* p0 = x_ext + ((size_t)(m0 ? (l0r + s - 1) : 0) * B_ + b0r) * E_;
        const float* p1 = x_ext + ((size_t)(m1 ? (l1r + s - 1) : 0) * B_ + b1r) * E_;

#pragma unroll 1
        for (int kc = 0; kc < NKC; kc++) {
            __syncthreads();
            {
                const uint4* srcW = g_cwp + CB0 + (((by * 3 + s) * NKC + kc) << 11);
#pragma unroll
                for (int it = 0; it < 8; it++)
                    smW[it * 256 + tid] = srcW[it * 256 + tid];
            }
            __syncthreads();

            uint32_t Ah[8][4];
#pragma unroll
            for (int c = 0; c < 8; c++) {
                int e0 = 128 * kc + 16 * c + 2 * t;
                float2 x00 = m0 ? *(const float2*)(p0 + e0)     : make_float2(0.f, 0.f);
                float2 x01 = m1 ? *(const float2*)(p1 + e0)     : make_float2(0.f, 0.f);
                float2 x10 = m0 ? *(const float2*)(p0 + e0 + 8) : make_float2(0.f, 0.f);
                float2 x11 = m1 ? *(const float2*)(p1 + e0 + 8) : make_float2(0.f, 0.f);
                Ah[c][0] = pack_h2(x00.x, x00.y);
                Ah[c][1] = pack_h2(x01.x, x01.y);
                Ah[c][2] = pack_h2(x10.x, x10.y);
                Ah[c][3] = pack_h2(x11.x, x11.y);
            }

#pragma unroll
            for (int c = 0; c < 8; c++) {
                const int bslot = c * 4 + t;
#pragma unroll
                for (int nt = 0; nt < 8; nt++) {
                    const int n = nt * 8 + g;
                    uint4 f4 = smW[n * 32 + (bslot ^ ((n & 1) * 4))];
                    mma16816_f16(acc[nt], Ah[c], f4.x, f4.y);
                    mma16816_f16(acc[nt], Ah[c], f4.z, f4.w);
                }
            }
        }
    }

    float* out = g_act1;
#pragma unroll
    for (int nt = 0; nt < 8; nt++) {
        int col = nt * 8 + 2 * t;
        float bb0 = __ldg(cb + f0 + col);
        float bb1 = __ldg(cb + f0 + col + 1);
        float z0 = lrelu(acc[nt][0] + bb0);
        float z1 = lrelu(acc[nt][1] + bb1);
        float z2 = lrelu(acc[nt][2] + bb0);
        float z3 = lrelu(acc[nt][3] + bb1);
        *(float2*)(out + (size_t)r0 * F_ + f0 + col) = make_float2(z0, z1);
        *(float2*)(out + (size_t)r1 * F_ + f0 + col) = make_float2(z2, z3);
        float s0 = z0 + z2, s1 = z1 + z3;
        float q0 = z0 * z0 + z2 * z2, q1 = z1 * z1 + z3 * z3;
#pragma unroll
        for (int o = 4; o < 32; o <<= 1) {
            s0 += __shfl_xor_sync(0xffffffffu, s0, o);
            s1 += __shfl_xor_sync(0xffffffffu, s1, o);
            q0 += __shfl_xor_sync(0xffffffffu, q0, o);
            q1 += __shfl_xor_sync(0xffffffffu, q1, o);
        }
        if (g == 0) {
            s_sum[w * 64 + col]     = s0;
            s_sum[w * 64 + col + 1] = s1;
            s_sq [w * 64 + col]     = q0;
            s_sq [w * 64 + col + 1] = q1;
        }
    }
    __syncthreads();
    if (tid < 64) {
        float s = 0.f, q = 0.f;
#pragma unroll
        for (int ww = 0; ww < 8; ww++) {
            s += s_sum[ww * 64 + tid];
            q += s_sq [ww * 64 + tid];
        }
        g_csum [0][f0 + tid][tile] = s;
        g_csum2[0][f0 + tid][tile] = q;
    }
}

// =================================================================================
// Conv layers 2..4 (EIN=256): RESIDENT weights — all 192KB staged once, then the
// 6-phase main loop is sync-free (A-build + MMA only).
// =================================================================================
constexpr int CSMEMF = 196608 + 2048 + 4096;   // weights + affine + partials

__global__ void __launch_bounds__(256) convF_mma(
    int src, int prev_layer,
    const float* __restrict__ ga_prev, const float* __restrict__ be_prev,
    int wbase,
    const float* __restrict__ cb,
    int dst, int stat_layer)
{
    constexpr int EIN = 256;
    constexpr int NKC = 2;
    extern __shared__ char smraw[];
    uint4*  smW     = (uint4*)smraw;                        // [6][2048] uint4
    float*  aff_a_s = (float*)(smraw + 196608);             // [256]
    float*  aff_b_s = aff_a_s + 256;
    float*  s_sum   = (float*)(smraw + 196608 + 2048);      // [8][64]
    float*  s_sq    = s_sum + 512;

    const int tile = blockIdx.x;
    const int by   = blockIdx.y;
    const int f0   = by * 64;
    const int row0 = tile * 128;
    const int tid  = threadIdx.x;
    const int w    = tid >> 5;
    const int lane = tid & 31;
    const int g    = lane >> 2;
    const int t    = lane & 3;

    // ---- affine from previous layer stats ----
    if (tid < 256) {
        int ch = tid;
        float s = 0.f, s2 = 0.f;
#pragma unroll
        for (int tt = 0; tt < RTILE; tt++) {
            s  += g_csum [prev_layer][ch][tt];
            s2 += g_csum2[prev_layer][ch][tt];
        }
        const float inv_n = 1.f / (float)NROW;
        float mean = s * inv_n;
        float var  = s2 * inv_n - mean * mean;
        float a = ga_prev[ch] * rsqrtf(var + 1e-5f);
        aff_a_s[ch] = a;
        aff_b_s[ch] = be_prev[ch] - mean * a;
    }

    // ---- stage ALL weights for this by (6 phases x 2048 uint4, contiguous) ----
    {
        const uint4* srcW = g_cwp + wbase + by * (3 * NKC * 2048);
#pragma unroll
        for (int it = 0; it < 48; it++)
            smW[it * 256 + tid] = srcW[it * 256 + tid];
    }
    __syncthreads();

    const int r0 = row0 + 16 * w + g;
    const int r1 = r0 + 8;
    const int b0r = r0 / 100, l0r = r0 - b0r * 100;
    const int b1r = r1 / 100, l1r = r1 - b1r * 100;

    const float* act_in = src ? g_act2 : g_act1;

    float acc[8][4];
#pragma unroll
    for (int nt = 0; nt < 8; nt++)
#pragma unroll
        for (int q = 0; q < 4; q++) acc[nt][q] = 0.f;

#pragma unroll 1
    for (int s = 0; s < 3; s++) {
        const bool m0 = (unsigned)(l0r + s - 1) < 100u;
        const bool m1 = (unsigned)(l1r + s - 1) < 100u;
        const float* p0 = act_in + (size_t)(m0 ? (r0 + s - 1) : r0) * EIN;
        const float* p1 = act_in + (size_t)(m1 ? (r1 + s - 1) : r1) * EIN;

#pragma unroll
        for (int kc = 0; kc < NKC; kc++) {
            const uint4* smWL = smW + ((s * NKC + kc) << 11);

            uint32_t Ah[8][4];
#pragma unroll
            for (int c = 0; c < 8; c++) {
                int e0 = 128 * kc + 16 * c + 2 * t;
                float2 x00 = m0 ? *(const float2*)(p0 + e0)     : make_float2(0.f, 0.f);
                float2 x01 = m1 ? *(const float2*)(p1 + e0)     : make_float2(0.f, 0.f);
                float2 x10 = m0 ? *(const float2*)(p0 + e0 + 8) : make_float2(0.f, 0.f);
                float2 x11 = m1 ? *(const float2*)(p1 + e0 + 8) : make_float2(0.f, 0.f);
                float a0 = aff_a_s[e0],     bA0 = aff_b_s[e0];
                float a1 = aff_a_s[e0 + 1], bA1 = aff_b_s[e0 + 1];
                float a8 = aff_a_s[e0 + 8], bA8 = aff_b_s[e0 + 8];
                float a9 = aff_a_s[e0 + 9], bA9 = aff_b_s[e0 + 9];
                if (m0) { x00.x = fmaf(a0, x00.x, bA0); x00.y = fmaf(a1, x00.y, bA1);
                          x10.x = fmaf(a8, x10.x, bA8); x10.y = fmaf(a9, x10.y, bA9); }
                if (m1) { x01.x = fmaf(a0, x01.x, bA0); x01.y = fmaf(a1, x01.y, bA1);
                          x11.x = fmaf(a8, x11.x, bA8); x11.y = fmaf(a9, x11.y, bA9); }
                Ah[c][0] = pack_h2(x00.x, x00.y);
                Ah[c][1] = pack_h2(x01.x, x01.y);
                Ah[c][2] = pack_h2(x10.x, x10.y);
                Ah[c][3] = pack_h2(x11.x, x11.y);
            }

#pragma unroll
            for (int c = 0; c < 8; c++) {
                const int bslot = c * 4 + t;
#pragma unroll
                for (int nt = 0; nt < 8; nt++) {
                    const int n = nt * 8 + g;
                    uint4 f4 = smWL[n * 32 + (bslot ^ ((n & 1) * 4))];
                    mma16816_f16(acc[nt], Ah[c], f4.x, f4.y);
                    mma16816_f16(acc[nt], Ah[c], f4.z, f4.w);
                }
            }
        }
    }

    float* out = dst ? g_act2 : g_act1;
#pragma unroll
    for (int nt = 0; nt < 8; nt++) {
        int col = nt * 8 + 2 * t;
        float bb0 = __ldg(cb + f0 + col);
        float bb1 = __ldg(cb + f0 + col + 1);
        float z0 = lrelu(acc[nt][0] + bb0);
        float z1 = lrelu(acc[nt][1] + bb1);
        float z2 = lrelu(acc[nt][2] + bb0);
        float z3 = lrelu(acc[nt][3] + bb1);
        *(float2*)(out + (size_t)r0 * F_ + f0 + col) = make_float2(z0, z1);
        *(float2*)(out + (size_t)r1 * F_ + f0 + col) = make_float2(z2, z3);
        float s0 = z0 + z2, s1 = z1 + z3;
        float q0 = z0 * z0 + z2 * z2, q1 = z1 * z1 + z3 * z3;
#pragma unroll
        for (int o = 4; o < 32; o <<= 1) {
            s0 += __shfl_xor_sync(0xffffffffu, s0, o);
            s1 += __shfl_xor_sync(0xffffffffu, s1, o);
            q0 += __shfl_xor_sync(0xffffffffu, q0, o);
            q1 += __shfl_xor_sync(0xffffffffu, q1, o);
        }
        if (g == 0) {
            s_sum[w * 64 + col]     = s0;
            s_sum[w * 64 + col + 1] = s1;
            s_sq [w * 64 + col]     = q0;
            s_sq [w * 64 + col + 1] = q1;
        }
    }
    __syncthreads();
    if (tid < 64) {
        float s = 0.f, q = 0.f;
#pragma unroll
        for (int ww = 0; ww < 8; ww++) {
            s += s_sum[ww * 64 + tid];
            q += s_sq [ww * 64 + tid];
        }
        g_csum [stat_layer][f0 + tid][tile] = s;
        g_csum2[stat_layer][f0 + tid][tile] = q;
    }
}

// =================================================================================
// A / C projections with fused hb, layer-4 affine, and pairwise weight packing.
// =================================================================================
constexpr int LT = 20;

__global__ void __launch_bounds__(256) ac_kernel(
    const float* __restrict__ W1, const float* __restrict__ b1,
    const float* __restrict__ h,
    const float* __restrict__ ga4, const float* __restrict__ be4,
    const float* __restrict__ W2, const float* __restrict__ W3,
    const float* __restrict__ W4)
{
    if (blockIdx.y == 5) {
        for (int idx = blockIdx.x * 256 + threadIdx.x; idx < 3 * 128 * 32;
             idx += 32 * 256) {
            int layer = idx >> 12;
            int rem   = idx & 4095;
            int n = rem >> 5;
            int s = rem & 31;
            int c = s >> 2;
            int t = s & 3;
            const float* W = layer == 0 ? W2 : (layer == 1 ? W3 : W4);
            uint32_t hw[2], lw[2];
#pragma unroll
            for (int j = 0; j < 2; j++) {
                int kw = 8 * c + 4 * j + t;
                float w0 = W[(size_t)(2 * kw) * 128 + n];
                float w1 = W[(size_t)(2 * kw + 1) * 128 + n];
                split2h(w0, w1, hw[j], lw[j]);
            }
            int slot = (c * 4 + t) ^ ((n & 1) * 4);
            g_wpack2[layer][n * 32 + slot] = make_uint4(hw[0], hw[1], lw[0], lw[1]);
        }
        return;
    }

    __shared__ float xf[LT][D_];
    __shared__ float aff_a_s[F_], aff_b_s[F_];
    __shared__ float hb_s[M_];

    const int b  = blockIdx.x;
    const int l0 = blockIdx.y * LT;
    const int t  = threadIdx.x;

    if (t < F_) {
        float s = 0.f, s2 = 0.f;
#pragma unroll
        for (int tt = 0; tt < RTILE; tt++) {
            s  += g_csum [3][t][tt];
            s2 += g_csum2[3][t][tt];
        }
        const float inv_n = 1.f / (float)NROW;
        float mean = s * inv_n;
        float var  = s2 * inv_n - mean * mean;
        float a = ga4[t] * rsqrtf(var + 1e-5f);
        aff_a_s[t] = a;
        aff_b_s[t] = be4[t] - mean * a;
    }
    __syncthreads();

    for (int c = t; c < LT * D_; c += 256) {
        int ll = c / D_;
        int ch = c - ll * D_;
        int l  = l0 + ll;
        float v;
        if (ch < F_) {
            v = aff_a_s[ch] * g_act2[(size_t)(b * 100 + l) * F_ + ch] + aff_b_s[ch];
        } else if (ch == F_) {
            v = ((float)l / 10.0f - 2.0f) * 0.5f;
        } else {
            v = ((float)(l % 10) - 2.0f) * 0.5f;
        }
        xf[ll][ch] = v;
    }

    if (t < 128) {
        const float* Wc = W1 + (size_t)(2 * D_) * M_;
        const float* hrow = h + (size_t)b * E_;
        float acc = b1[t];
#pragma unroll 4
        for (int k = 0; k < E_; k++) acc += hrow[k] * Wc[(size_t)k * M_ + t];
        hb_s[t] = acc;
    }
    __syncthreads();

    const int n  = t & 127;
    const int lg = t >> 7;

    float accA[LT / 2], accC[LT / 2];
#pragma unroll
    for (int i = 0; i < LT / 2; i++) { accA[i] = 0.f; accC[i] = 0.f; }

    const float* Wa = W1;
    const float* Wb = W1 + (size_t)D_ * M_;
#pragma unroll 2
    for (int c = 0; c < D_; c++) {
        float wa = Wa[(size_t)c * M_ + n];
        float wb = Wb[(size_t)c * M_ + n];
#pragma unroll
        for (int i = 0; i < LT / 2; i++) {
            float x = xf[2 * i + lg][c];
            accA[i] += x * wa;
            accC[i] += x * wb;
        }
    }
    float hbv = hb_s[n];
#pragma unroll
    for (int i = 0; i < LT / 2; i++) {
        int l = l0 + 2 * i + lg;
        g_A[((size_t)b * L_ + l) * M_ + n] = accA[i];
        g_C[((size_t)b * L_ + l) * M_ + n] = accC[i] + hbv;
    }
}

// =================================================================================
// PERSISTENT tensor-core pairwise relation kernel (R14, proven).
// =================================================================================
constexpr int SMEM_PW = 3 * 65536 + 4096;   // 200,704 B
constexpr int PW_GRID = 148;

__global__ void __launch_bounds__(256) pairwise_mma(
    const float* __restrict__ b2, const float* __restrict__ b3,
    const float* __restrict__ b4)
{
    extern __shared__ char smraw[];
    uint4* smW    = (uint4*)smraw;
    float* s_part = (float*)(smraw + 3 * 65536);

    const int tid  = threadIdx.x;
    const int w    = tid >> 5;
    const int lane = tid & 31;
    const int g    = lane >> 2;
    const int t    = lane & 3;

    {
        const uint4* src = g_wpack2[0];
#pragma unroll
        for (int it = 0; it < 48; it++)
            smW[it * 256 + tid] = src[it * 256 + tid];
    }
    __syncthreads();

    for (int job = blockIdx.x; job < NJOB; job += PW_GRID) {
        const int b    = job & 31;
        const int tile = job >> 5;
        const int row0 = tile * 128;
        const int r0 = row0 + 16 * w + g;
        const int r1 = r0 + 8;

        uint32_t Ah[8][4];
        {
            int rc0 = r0 < NPAIR ? r0 : 0;
            int rc1 = r1 < NPAIR ? r1 : 0;
            int i0 = rc0 / 100, j0 = rc0 - (rc0 / 100) * 100;
            int i1 = rc1 / 100, j1 = rc1 - (rc1 / 100) * 100;
            const float2* C0 = (const float2*)(g_C + ((size_t)b * L_ + i0) * M_);
            const float2* A0 = (const float2*)(g_A + ((size_t)b * L_ + j0) * M_);
            const float2* C1 = (const float2*)(g_C + ((size_t)b * L_ + i1) * M_);
            const float2* A1 = (const float2*)(g_A + ((size_t)b * L_ + j1) * M_);
#pragma unroll
            for (int c = 0; c < 8; c++) {
                int idx = 8 * c + t;
                float2 cc, aa;
                cc = C0[idx];     aa = A0[idx];
                Ah[c][0] = pack_h2(lrelu(cc.x + aa.x), lrelu(cc.y + aa.y));
                cc = C1[idx];     aa = A1[idx];
                Ah[c][1] = pack_h2(lrelu(cc.x + aa.x), lrelu(cc.y + aa.y));
                cc = C0[idx + 4]; aa = A0[idx + 4];
                Ah[c][2] = pack_h2(lrelu(cc.x + aa.x), lrelu(cc.y + aa.y));
                cc = C1[idx + 4]; aa = A1[idx + 4];
                Ah[c][3] = pack_h2(lrelu(cc.x + aa.x), lrelu(cc.y + aa.y));
            }
        }

#pragma unroll
        for (int layer = 0; layer < 3; layer++) {
            const uint4* smWL = smW + (layer << 12);
            float acc[16][4];
#pragma unroll
            for (int nt = 0; nt < 16; nt++)
#pragma unroll
                for (int q = 0; q < 4; q++) acc[nt][q] = 0.f;

#pragma unroll
            for (int c = 0; c < 8; c++) {
                const int base_slot = c * 4 + t;
#pragma unroll
                for (int nt = 0; nt < 16; nt++) {
                    const int n = nt * 8 + g;
                    uint4 f4 = smWL[n * 32 + (base_slot ^ ((n & 1) * 4))];
                    mma16816_f16(acc[nt], Ah[c], f4.x, f4.y);
                    mma16816_f16(acc[nt], Ah[c], f4.z, f4.w);
                }
            }

            if (layer < 2) {
                const float* bias = layer == 0 ? b2 : b3;
#pragma unroll
                for (int nt = 0; nt < 16; nt++) {
                    int col = nt * 8 + 2 * t;
                    float bb0 = __ldg(bias + col);
                    float bb1 = __ldg(bias + col + 1);
                    float z0 = lrelu(acc[nt][0] + bb0);
                    float z1 = lrelu(acc[nt][1] + bb1);
                    float z2 = lrelu(acc[nt][2] + bb0);
                    float z3 = lrelu(acc[nt][3] + bb1);
                    int c2  = nt >> 1;
                    int off = (nt & 1) * 2;
                    Ah[c2][off]     = pack_h2(z0, z1);
                    Ah[c2][off + 1] = pack_h2(z2, z3);
                }
            } else {
                const bool live0 = r0 < NPAIR;
                const bool live1 = r1 < NPAIR;
#pragma unroll
                for (int nt = 0; nt < 16; nt++) {
                    int col = nt * 8 + 2 * t;
                    float bb0 = __ldg(b4 + col);
                    float bb1 = __ldg(b4 + col + 1);
                    float z0 = live0 ? lrelu(acc[nt][0] + bb0) : 0.f;
                    float z1 = live0 ? lrelu(acc[nt][1] + bb1) : 0.f;
                    float z2 = live1 ? lrelu(acc[nt][2] + bb0) : 0.f;
                    float z3 = live1 ? lrelu(acc[nt][3] + bb1) : 0.f;
                    float v0 = z0 + z2;
                    float v1 = z1 + z3;
#pragma unroll
                    for (int o = 4; o < 32; o <<= 1) {
                        v0 += __shfl_xor_sync(0xffffffffu, v0, o);
                        v1 += __shfl_xor_sync(0xffffffffu, v1, o);
                    }
                    if (g == 0) {
                        s_part[w * 128 + col]     = v0;
                        s_part[w * 128 + col + 1] = v1;
                    }
                }
                __syncthreads();
                if (tid < 128) {
                    float ss = 0.f;
#pragma unroll
                    for (int ww = 0; ww < 8; ww++) ss += s_part[ww * 128 + tid];
                    g_part[((size_t)b * NTILE + tile) * M_ + tid] = ss;
                }
                __syncthreads();
            }
        }
    }
}

// =================================================================================
// Final decoder (unchanged)
// =================================================================================
__global__ void __launch_bounds__(128) final_kernel(
    const float* __restrict__ F1, const float* __restrict__ fb1,
    const float* __restrict__ F2, const float* __restrict__ fb2,
    float* __restrict__ out)
{
    const int b = blockIdx.x;
    const int t = threadIdx.x;
    __shared__ float s_s[M_], t_s[M_];

    float acc = 0.f;
    for (int i = 0; i < NTILE; i++)
        acc += g_part[((size_t)b * NTILE + i) * M_ + t];
    s_s[t] = acc;
    __syncthreads();

    float a2 = fb1[t];
#pragma unroll 4
    for (int k = 0; k < M_; k++) a2 += s_s[k] * F1[(size_t)k * M_ + t];
    t_s[t] = lrelu(a2);
    __syncthreads();

    for (int m = t; m < 512; m += 128) {
        float a3 = fb2[m];
#pragma unroll 4
        for (int k = 0; k < M_; k++) a3 += t_s[k] * F2[(size_t)k * 512 + m];
        out[(size_t)b * 512 + m] = lrelu(a3);
    }
}

// =================================================================================
// launcher
// =================================================================================
extern "C" void kernel_launch(void* const* d_in, const int* in_sizes, int n_in,
                              void* d_out, int out_size)
{
    (void)in_sizes; (void)n_in; (void)out_size;

    const float* x   = (const float*)d_in[0];
    const float* h   = (const float*)d_in[1];
    const float* cw1 = (const float*)d_in[2];
    const float* cb1 = (const float*)d_in[3];
    const float* ga1 = (const float*)d_in[4];
    const float* be1 = (const float*)d_in[5];
    const float* cw2 = (const float*)d_in[6];
    const float* cb2 = (const float*)d_in[7];
    const float* ga2 = (const float*)d_in[8];
    const float* be2 = (const float*)d_in[9];
    const float* cw3 = (const float*)d_in[10];
    const float* cb3 = (const float*)d_in[11];
    const float* ga3 = (const float*)d_in[12];
    const float* be3 = (const float*)d_in[13];
    const float* cw4 = (const float*)d_in[14];
    const float* cb4 = (const float*)d_in[15];
    const float* ga4 = (const float*)d_in[16];
    const float* be4 = (const float*)d_in[17];
    const float* W1  = (const float*)d_in[18];
    const float* b1  = (const float*)d_in[19];
    const float* W2  = (const float*)d_in[20];
    const float* b2  = (const float*)d_in[21];
    const float* W3  = (const float*)d_in[22];
    const float* b3  = (const float*)d_in[23];
    const float* W4  = (const float*)d_in[24];
    const float* b4  = (const float*)d_in[25];
    const float* F1  = (const float*)d_in[26];
    const float* fb1 = (const float*)d_in[27];
    const float* F2  = (const float*)d_in[28];
    const float* fb2 = (const float*)d_in[29];
    float* out = (float*)d_out;

    cudaFuncSetAttribute(conv1_mma,
                         cudaFuncAttributeMaxDynamicSharedMemorySize, CSMEM1);
    cudaFuncSetAttribute(convF_mma,
                         cudaFuncAttributeMaxDynamicSharedMemorySize, CSMEMF);
    cudaFuncSetAttribute(pairwise_mma,
                         cudaFuncAttributeMaxDynamicSharedMemorySize, SMEM_PW);

    dim3 cgrid(RTILE, 4);

    // 0: one-time conv weight pack
    pack_conv<<<(CWP_TOTAL + 255) / 256, 256>>>(cw1, cw2, cw3, cw4);

    // 1: conv layer 1 (phase-staged)
    conv1_mma<<<cgrid, 256, CSMEM1>>>(x, cb1);

    // 2..4: conv layers 2-4 (resident weights, sync-free main loop)
    convF_mma<<<cgrid, 256, CSMEMF>>>(0, 0, ga1, be1, CB1, cb2, 1, 1);
    convF_mma<<<cgrid, 256, CSMEMF>>>(1, 1, ga2, be2, CB2, cb3, 0, 2);
    convF_mma<<<cgrid, 256, CSMEMF>>>(0, 2, ga3, be3, CB3, cb4, 1, 3);

    // 5: projections (fused hb + layer-4 affine + pairwise weight packing)
    ac_kernel<<<dim3(B_, 6), 256>>>(W1, b1, h, ga4, be4, W2, W3, W4);

    // 6: persistent tensor-core pairwise chain
    pairwise_mma<<<PW_GRID, 256, SMEM_PW>>>(b2, b3, b4);

    // 7: decoder
    final_kernel<<<B_, 128>>>(F1, fb1, F2, fb2, out);
}

// round 16
// speedup vs baseline: 1.0229x; 1.0229x over previous
#include <cuda_runtime.h>
#include <cuda_fp16.h>
#include <cstdint>

#define DEV_INLINE __device__ __forceinline__

constexpr int L_   = 100;
constexpr int B_   = 32;
constexpr int E_   = 512;
constexpr int F_   = 256;
constexpr int M_   = 128;
constexpr int D_   = 258;
constexpr int NPAIR = L_ * L_;                 // 10000
constexpr int NTILE = (NPAIR + 127) / 128;     // 79
constexpr int NJOB  = NTILE * B_;              // 2528
constexpr int NROW  = B_ * L_;                 // 3200 = 25 * 128
constexpr int RTILE = 25;

// packed conv-weight fragment array bases (uint4 units)
constexpr int CB0 = 0;
constexpr int CB1 = 98304;
constexpr int CB2 = 147456;
constexpr int CB3 = 196608;
constexpr int CWP_TOTAL = 245760;

// ---------------- scratch (device globals; no allocation allowed) ----------------
__device__ float g_act1[NROW * F_];
__device__ float g_act2[NROW * F_];
__device__ float g_csum [4][F_][32];
__device__ float g_csum2[4][F_][32];
__device__ float g_A[B_ * L_ * M_];
__device__ float g_C[B_ * L_ * M_];
__device__ float g_part[B_ * NTILE * M_];
__device__ __align__(16) uint4 g_wpack2[3][128 * 32];   // pairwise weights
__device__ __align__(16) uint4 g_cwp[CWP_TOTAL];        // conv weights (fragments)

DEV_INLINE float lrelu(float z) { return fmaxf(z, 0.f) + 0.1f * fminf(z, 0.f); }

DEV_INLINE uint32_t pack_h2(float x0, float x1) {
    __half2 h = __floats2half2_rn(x0, x1);
    return *reinterpret_cast<uint32_t*>(&h);
}

DEV_INLINE void split2h(float x0, float x1, uint32_t& hi, uint32_t& lo) {
    __half h0 = __float2half_rn(x0);
    __half h1 = __float2half_rn(x1);
    float r0 = x0 - __half2float(h0);
    float r1 = x1 - __half2float(h1);
    __half2 hh = __halves2half2(h0, h1);
    hi = *reinterpret_cast<uint32_t*>(&hh);
    lo = pack_h2(r0, r1);
}

DEV_INLINE void mma16816_f16(float c[4], const uint32_t a[4], uint32_t b0, uint32_t b1) {
    asm volatile(
        "mma.sync.aligned.m16n8k16.row.col.f32.f16.f16.f32 "
        "{%0,%1,%2,%3}, {%4,%5,%6,%7}, {%8,%9}, {%0,%1,%2,%3};"
        : "+f"(c[0]), "+f"(c[1]), "+f"(c[2]), "+f"(c[3])
        : "r"(a[0]), "r"(a[1]), "r"(a[2]), "r"(a[3]), "r"(b0), "r"(b1));
}

// =================================================================================
// One-time conv weight pack (fp16 hi/lo fragment uint4s; layout matches conv MMA).
// =================================================================================
__global__ void __launch_bounds__(256) pack_conv(
    const float* __restrict__ cw1, const float* __restrict__ cw2,
    const float* __restrict__ cw3, const float* __restrict__ cw4)
{
    int idx = blockIdx.x * 256 + threadIdx.x;
    if (idx >= CWP_TOTAL) return;
    const float* cw; int EIN, NKC, rem;
    if (idx < CB1)      { rem = idx;       cw = cw1; EIN = 512; NKC = 4; }
    else if (idx < CB2) { rem = idx - CB1; cw = cw2; EIN = 256; NKC = 2; }
    else if (idx < CB3) { rem = idx - CB2; cw = cw3; EIN = 256; NKC = 2; }
    else                { rem = idx - CB3; cw = cw4; EIN = 256; NKC = 2; }
    int per_by = 3 * NKC * 2048;
    int by = rem / per_by;
    int r2 = rem - by * per_by;
    int s  = r2 / (NKC * 2048);
    int r3 = r2 - s * (NKC * 2048);
    int kc = r3 >> 11;
    int id = r3 & 2047;
    int n  = id >> 5;
    int j  = id & 31;
    int jj = j ^ ((n & 1) * 4);
    int e0 = 128 * kc + 16 * (jj >> 2) + 2 * (jj & 3);
    const float* wp = cw + ((size_t)(by * 64 + n) * EIN + e0) * 3 + s;
    float v0 = wp[0], v1 = wp[3], v2 = wp[24], v3 = wp[27];
    uint32_t h01, l01, h23, l23;
    split2h(v0, v1, h01, l01);
    split2h(v2, v3, h23, l23);
    g_cwp[idx] = make_uint4(h01, h23, l01, l23);
}

// =================================================================================
// Conv1d v3 (K=3, pad 1) + bias + leakyReLU + fused BN stats.
// smem activation tile: rows [row0-1, row0+128] x 128ch, pre-affined + fp16-packed
// once per kc (coalesced), reused across all 3 shifts. A-build = pure LDS.
// 2 blocks/SM for cross-block MMA/staging overlap.
// =================================================================================
constexpr int AP    = 68;                       // smA pitch (uint32): bank = 4g+t, conflict-free
constexpr int SMA_B = 130 * AP * 4;             // 35,360 B
constexpr int CSMEM3 = 32768 + SMA_B + 2048 + 4096;   // 74,272 B

template <int EIN, bool FIRST>
__global__ void __launch_bounds__(256, 2) conv_v3(
    const float* __restrict__ x_ext,
    int src, int prev_layer,
    const float* __restrict__ ga_prev, const float* __restrict__ be_prev,
    int wbase,
    const float* __restrict__ cb,
    int dst, int stat_layer)
{
    constexpr int NKC = EIN / 128;
    extern __shared__ char smraw[];
    uint4*    smW     = (uint4*)smraw;                         // 2048 uint4 = 32KB
    uint32_t* smA     = (uint32_t*)(smraw + 32768);            // [130][AP]
    float*    aff_a_s = (float*)(smraw + 32768 + SMA_B);       // [256]
    float*    aff_b_s = aff_a_s + 256;
    float*    s_sum   = (float*)(smraw + 32768 + SMA_B + 2048);
    float*    s_sq    = s_sum + 512;

    const int tile = blockIdx.x;       // 0..24
    const int by   = blockIdx.y;       // 0..3
    const int f0   = by * 64;
    const int row0 = tile * 128;
    const int tid  = threadIdx.x;
    const int w    = tid >> 5;
    const int lane = tid & 31;
    const int g    = lane >> 2;
    const int t    = lane & 3;

    if (!FIRST) {
        if (tid < 256) {
            int ch = tid;
            float s = 0.f, s2 = 0.f;
#pragma unroll
            for (int tt = 0; tt < RTILE; tt++) {
                s  += g_csum [prev_layer][ch][tt];
                s2 += g_csum2[prev_layer][ch][tt];
            }
            const float inv_n = 1.f / (float)NROW;
            float mean = s * inv_n;
            float var  = s2 * inv_n - mean * mean;
            float a = ga_prev[ch] * rsqrtf(var + 1e-5f);
            aff_a_s[ch] = a;
            aff_b_s[ch] = be_prev[ch] - mean * a;
        }
        __syncthreads();   // affine visible to A staging
    }

    const int r0 = row0 + 16 * w + g;
    const int r1 = r0 + 8;
    const int l0r = r0 % 100;
    const int l1r = r1 % 100;

    const float* act_in = src ? g_act2 : g_act1;

    float acc[8][4];
#pragma unroll
    for (int nt = 0; nt < 8; nt++)
#pragma unroll
        for (int q = 0; q < 4; q++) acc[nt][q] = 0.f;

#pragma unroll 1
    for (int kc = 0; kc < NKC; kc++) {
        __syncthreads();   // previous phase A/W reads done before restaging smA

        // ---- stage activation tile for this kc (coalesced, affined, packed) ----
        for (int i = tid; i < 130 * 64; i += 256) {
            int lr = i >> 6;
            int cp = i & 63;
            int gr = row0 - 1 + lr;
            gr = gr < 0 ? 0 : (gr > NROW - 1 ? NROW - 1 : gr);
            float2 v;
            if (FIRST) {
                int bb = gr / 100;
                int ll = gr - bb * 100;
                v = *(const float2*)(x_ext + ((size_t)ll * B_ + bb) * E_ + 128 * kc + 2 * cp);
            } else {
                v = *(const float2*)(act_in + (size_t)gr * EIN + 128 * kc + 2 * cp);
                int ch = 128 * kc + 2 * cp;
                v.x = fmaf(aff_a_s[ch],     v.x, aff_b_s[ch]);
                v.y = fmaf(aff_a_s[ch + 1], v.y, aff_b_s[ch + 1]);
            }
            smA[lr * AP + cp] = pack_h2(v.x, v.y);
        }

#pragma unroll 1
        for (int s = 0; s < 3; s++) {
            __syncthreads();   // prior phase smW reads done (first pass: smA writes done)
            {
                const uint4* srcW = g_cwp + wbase + (((by * 3 + s) * NKC + kc) << 11);
#pragma unroll
                for (int it = 0; it < 8; it++)
                    smW[it * 256 + tid] = srcW[it * 256 + tid];
            }
            __syncthreads();

            const bool m0 = (unsigned)(l0r + s - 1) < 100u;
            const bool m1 = (unsigned)(l1r + s - 1) < 100u;
            const int lr0 = 16 * w + g + s;        // local row of fragment slot 0
            const int lr1 = lr0 + 8;

            uint32_t Ah[8][4];
#pragma unroll
            for (int c = 0; c < 8; c++) {
                int base0 = lr0 * AP + 8 * c + t;
                int base1 = lr1 * AP + 8 * c + t;
                Ah[c][0] = m0 ? smA[base0]     : 0u;
                Ah[c][1] = m1 ? smA[base1]     : 0u;
                Ah[c][2] = m0 ? smA[base0 + 4] : 0u;
                Ah[c][3] = m1 ? smA[base1 + 4] : 0u;
            }

#pragma unroll
            for (int c = 0; c < 8; c++) {
                const int bslot = c * 4 + t;
#pragma unroll
                for (int nt = 0; nt < 8; nt++) {
                    const int n = nt * 8 + g;
                    uint4 f4 = smW[n * 32 + (bslot ^ ((n & 1) * 4))];
                    mma16816_f16(acc[nt], Ah[c], f4.x, f4.y);
                    mma16816_f16(acc[nt], Ah[c], f4.z, f4.w);
                }
            }
        }
    }

    // ---- epilogue: bias + lrelu, write act, fused BN partial stats ----
    float* out = dst ? g_act2 : g_act1;
#pragma unroll
    for (int nt = 0; nt < 8; nt++) {
        int col = nt * 8 + 2 * t;
        float bb0 = __ldg(cb + f0 + col);
        float bb1 = __ldg(cb + f0 + col + 1);
        float z0 = lrelu(acc[nt][0] + bb0);
        float z1 = lrelu(acc[nt][1] + bb1);
        float z2 = lrelu(acc[nt][2] + bb0);
        float z3 = lrelu(acc[nt][3] + bb1);
        *(float2*)(out + (size_t)r0 * F_ + f0 + col) = make_float2(z0, z1);
        *(float2*)(out + (size_t)r1 * F_ + f0 + col) = make_float2(z2, z3);
        float s0 = z0 + z2, s1 = z1 + z3;
        float q0 = z0 * z0 + z2 * z2, q1 = z1 * z1 + z3 * z3;
#pragma unroll
        for (int o = 4; o < 32; o <<= 1) {
            s0 += __shfl_xor_sync(0xffffffffu, s0, o);
            s1 += __shfl_xor_sync(0xffffffffu, s1, o);
            q0 += __shfl_xor_sync(0xffffffffu, q0, o);
            q1 += __shfl_xor_sync(0xffffffffu, q1, o);
        }
        if (g == 0) {
            s_sum[w * 64 + col]     = s0;
            s_sum[w * 64 + col + 1] = s1;
            s_sq [w * 64 + col]     = q0;
            s_sq [w * 64 + col + 1] = q1;
        }
    }
    __syncthreads();
    if (tid < 64) {
        float s = 0.f, q = 0.f;
#pragma unroll
        for (int ww = 0; ww < 8; ww++) {
            s += s_sum[ww * 64 + tid];
            q += s_sq [ww * 64 + tid];
        }
        g_csum [stat_layer][f0 + tid][tile] = s;
        g_csum2[stat_layer][f0 + tid][tile] = q;
    }
}

// =================================================================================
// A / C projections with fused hb, layer-4 affine, and pairwise weight packing.
// =================================================================================
constexpr int LT = 20;

__global__ void __launch_bounds__(256) ac_kernel(
    const float* __restrict__ W1, const float* __restrict__ b1,
    const float* __restrict__ h,
    const float* __restrict__ ga4, const float* __restrict__ be4,
    const float* __restrict__ W2, const float* __restrict__ W3,
    const float* __restrict__ W4)
{
    if (blockIdx.y == 5) {
        for (int idx = blockIdx.x * 256 + threadIdx.x; idx < 3 * 128 * 32;
             idx += 32 * 256) {
            int layer = idx >> 12;
            int rem   = idx & 4095;
            int n = rem >> 5;
            int s = rem & 31;
            int c = s >> 2;
            int t = s & 3;
            const float* W = layer == 0 ? W2 : (layer == 1 ? W3 : W4);
            uint32_t hw[2], lw[2];
#pragma unroll
            for (int j = 0; j < 2; j++) {
                int kw = 8 * c + 4 * j + t;
                float w0 = W[(size_t)(2 * kw) * 128 + n];
                float w1 = W[(size_t)(2 * kw + 1) * 128 + n];
                split2h(w0, w1, hw[j], lw[j]);
            }
            int slot = (c * 4 + t) ^ ((n & 1) * 4);
            g_wpack2[layer][n * 32 + slot] = make_uint4(hw[0], hw[1], lw[0], lw[1]);
        }
        return;
    }

    __shared__ float xf[LT][D_];
    __shared__ float aff_a_s[F_], aff_b_s[F_];
    __shared__ float hb_s[M_];

    const int b  = blockIdx.x;
    const int l0 = blockIdx.y * LT;
    const int t  = threadIdx.x;

    if (t < F_) {
        float s = 0.f, s2 = 0.f;
#pragma unroll
        for (int tt = 0; tt < RTILE; tt++) {
            s  += g_csum [3][t][tt];
            s2 += g_csum2[3][t][tt];
        }
        const float inv_n = 1.f / (float)NROW;
        float mean = s * inv_n;
        float var  = s2 * inv_n - mean * mean;
        float a = ga4[t] * rsqrtf(var + 1e-5f);
        aff_a_s[t] = a;
        aff_b_s[t] = be4[t] - mean * a;
    }
    __syncthreads();

    for (int c = t; c < LT * D_; c += 256) {
        int ll = c / D_;
        int ch = c - ll * D_;
        int l  = l0 + ll;
        float v;
        if (ch < F_) {
            v = aff_a_s[ch] * g_act2[(size_t)(b * 100 + l) * F_ + ch] + aff_b_s[ch];
        } else if (ch == F_) {
            v = ((float)l / 10.0f - 2.0f) * 0.5f;
        } else {
            v = ((float)(l % 10) - 2.0f) * 0.5f;
        }
        xf[ll][ch] = v;
    }

    if (t < 128) {
        const float* Wc = W1 + (size_t)(2 * D_) * M_;
        const float* hrow = h + (size_t)b * E_;
        float acc = b1[t];
#pragma unroll 4
        for (int k = 0; k < E_; k++) acc += hrow[k] * Wc[(size_t)k * M_ + t];
        hb_s[t] = acc;
    }
    __syncthreads();

    const int n  = t & 127;
    const int lg = t >> 7;

    float accA[LT / 2], accC[LT / 2];
#pragma unroll
    for (int i = 0; i < LT / 2; i++) { accA[i] = 0.f; accC[i] = 0.f; }

    const float* Wa = W1;
    const float* Wb = W1 + (size_t)D_ * M_;
#pragma unroll 2
    for (int c = 0; c < D_; c++) {
        float wa = Wa[(size_t)c * M_ + n];
        float wb = Wb[(size_t)c * M_ + n];
#pragma unroll
        for (int i = 0; i < LT / 2; i++) {
            float x = xf[2 * i + lg][c];
            accA[i] += x * wa;
            accC[i] += x * wb;
        }
    }
    float hbv = hb_s[n];
#pragma unroll
    for (int i = 0; i < LT / 2; i++) {
        int l = l0 + 2 * i + lg;
        g_A[((size_t)b * L_ + l) * M_ + n] = accA[i];
        g_C[((size_t)b * L_ + l) * M_ + n] = accC[i] + hbv;
    }
}

// =================================================================================
// PERSISTENT tensor-core pairwise relation kernel (R14, at MMA floor).
// =================================================================================
constexpr int SMEM_PW = 3 * 65536 + 4096;   // 200,704 B
constexpr int PW_GRID = 148;

__global__ void __launch_bounds__(256) pairwise_mma(
    const float* __restrict__ b2, const float* __restrict__ b3,
    const float* __restrict__ b4)
{
    extern __shared__ char smraw[];
    uint4* smW    = (uint4*)smraw;
    float* s_part = (float*)(smraw + 3 * 65536);

    const int tid  = threadIdx.x;
    const int w    = tid >> 5;
    const int lane = tid & 31;
    const int g    = lane >> 2;
    const int t    = lane & 3;

    {
        const uint4* src = g_wpack2[0];
#pragma unroll
        for (int it = 0; it < 48; it++)
            smW[it * 256 + tid] = src[it * 256 + tid];
    }
    __syncthreads();

    for (int job = blockIdx.x; job < NJOB; job += PW_GRID) {
        const int b    = job & 31;
        const int tile = job >> 5;
        const int row0 = tile * 128;
        const int r0 = row0 + 16 * w + g;
        const int r1 = r0 + 8;

        uint32_t Ah[8][4];
        {
            int rc0 = r0 < NPAIR ? r0 : 0;
            int rc1 = r1 < NPAIR ? r1 : 0;
            int i0 = rc0 / 100, j0 = rc0 - (rc0 / 100) * 100;
            int i1 = rc1 / 100, j1 = rc1 - (rc1 / 100) * 100;
            const float2* C0 = (const float2*)(g_C + ((size_t)b * L_ + i0) * M_);
            const float2* A0 = (const float2*)(g_A + ((size_t)b * L_ + j0) * M_);
            const float2* C1 = (const float2*)(g_C + ((size_t)b * L_ + i1) * M_);
            const float2* A1 = (const float2*)(g_A + ((size_t)b * L_ + j1) * M_);
#pragma unroll
            for (int c = 0; c < 8; c++) {
                int idx = 8 * c + t;
                float2 cc, aa;
                cc = C0[idx];     aa = A0[idx];
                Ah[c][0] = pack_h2(lrelu(cc.x + aa.x), lrelu(cc.y + aa.y));
                cc = C1[idx];     aa = A1[idx];
                Ah[c][1] = pack_h2(lrelu(cc.x + aa.x), lrelu(cc.y + aa.y));
                cc = C0[idx + 4]; aa = A0[idx + 4];
                Ah[c][2] = pack_h2(lrelu(cc.x + aa.x), lrelu(cc.y + aa.y));
                cc = C1[idx + 4]; aa = A1[idx + 4];
                Ah[c][3] = pack_h2(lrelu(cc.x + aa.x), lrelu(cc.y + aa.y));
            }
        }

#pragma unroll
        for (int layer = 0; layer < 3; layer++) {
            const uint4* smWL = smW + (layer << 12);
            float acc[16][4];
#pragma unroll
            for (int nt = 0; nt < 16; nt++)
#pragma unroll
                for (int q = 0; q < 4; q++) acc[nt][q] = 0.f;

#pragma unroll
            for (int c = 0; c < 8; c++) {
                const int base_slot = c * 4 + t;
#pragma unroll
                for (int nt = 0; nt < 16; nt++) {
                    const int n = nt * 8 + g;
                    uint4 f4 = smWL[n * 32 + (base_slot ^ ((n & 1) * 4))];
                    mma16816_f16(acc[nt], Ah[c], f4.x, f4.y);
                    mma16816_f16(acc[nt], Ah[c], f4.z, f4.w);
                }
            }

            if (layer < 2) {
                const float* bias = layer == 0 ? b2 : b3;
#pragma unroll
                for (int nt = 0; nt < 16; nt++) {
                    int col = nt * 8 + 2 * t;
                    float bb0 = __ldg(bias + col);
                    float bb1 = __ldg(bias + col + 1);
                    float z0 = lrelu(acc[nt][0] + bb0);
                    float z1 = lrelu(acc[nt][1] + bb1);
                    float z2 = lrelu(acc[nt][2] + bb0);
                    float z3 = lrelu(acc[nt][3] + bb1);
                    int c2  = nt >> 1;
                    int off = (nt & 1) * 2;
                    Ah[c2][off]     = pack_h2(z0, z1);
                    Ah[c2][off + 1] = pack_h2(z2, z3);
                }
            } else {
                const bool live0 = r0 < NPAIR;
                const bool live1 = r1 < NPAIR;
#pragma unroll
                for (int nt = 0; nt < 16; nt++) {
                    int col = nt * 8 + 2 * t;
                    float bb0 = __ldg(b4 + col);
                    float bb1 = __ldg(b4 + col + 1);
                    float z0 = live0 ? lrelu(acc[nt][0] + bb0) : 0.f;
                    float z1 = live0 ? lrelu(acc[nt][1] + bb1) : 0.f;
                    float z2 = live1 ? lrelu(acc[nt][2] + bb0) : 0.f;
                    float z3 = live1 ? lrelu(acc[nt][3] + bb1) : 0.f;
                    float v0 = z0 + z2;
                    float v1 = z1 + z3;
#pragma unroll
                    for (int o = 4; o < 32; o <<= 1) {
                        v0 += __shfl_xor_sync(0xffffffffu, v0, o);
                        v1 += __shfl_xor_sync(0xffffffffu, v1, o);
                    }
                    if (g == 0) {
                        s_part[w * 128 + col]     = v0;
                        s_part[w * 128 + col + 1] = v1;
                    }
                }
                __syncthreads();
                if (tid < 128) {
                    float ss = 0.f;
#pragma unroll
                    for (int ww = 0; ww < 8; ww++) ss += s_part[ww * 128 + tid];
                    g_part[((size_t)b * NTILE + tile) * M_ + tid] = ss;
                }
                __syncthreads();
            }
        }
    }
}

// =================================================================================
// Final decoder (unchanged)
// =================================================================================
__global__ void __launch_bounds__(128) final_kernel(
    const float* __restrict__ F1, const float* __restrict__ fb1,
    const float* __restrict__ F2, const float* __restrict__ fb2,
    float* __restrict__ out)
{
    const int b = blockIdx.x;
    const int t = threadIdx.x;
    __shared__ float s_s[M_], t_s[M_];

    float acc = 0.f;
    for (int i = 0; i < NTILE; i++)
        acc += g_part[((size_t)b * NTILE + i) * M_ + t];
    s_s[t] = acc;
    __syncthreads();

    float a2 = fb1[t];
#pragma unroll 4
    for (int k = 0; k < M_; k++) a2 += s_s[k] * F1[(size_t)k * M_ + t];
    t_s[t] = lrelu(a2);
    __syncthreads();

    for (int m = t; m < 512; m += 128) {
        float a3 = fb2[m];
#pragma unroll 4
        for (int k = 0; k < M_; k++) a3 += t_s[k] * F2[(size_t)k * 512 + m];
        out[(size_t)b * 512 + m] = lrelu(a3);
    }
}

// =================================================================================
// launcher
// =================================================================================
extern "C" void kernel_launch(void* const* d_in, const int* in_sizes, int n_in,
                              void* d_out, int out_size)
{
    (void)in_sizes; (void)n_in; (void)out_size;

    const float* x   = (const float*)d_in[0];
    const float* h   = (const float*)d_in[1];
    const float* cw1 = (const float*)d_in[2];
    const float* cb1 = (const float*)d_in[3];
    const float* ga1 = (const float*)d_in[4];
    const float* be1 = (const float*)d_in[5];
    const float* cw2 = (const float*)d_in[6];
    const float* cb2 = (const float*)d_in[7];
    const float* ga2 = (const float*)d_in[8];
    const float* be2 = (const float*)d_in[9];
    const float* cw3 = (const float*)d_in[10];
    const float* cb3 = (const float*)d_in[11];
    const float* ga3 = (const float*)d_in[12];
    const float* be3 = (const float*)d_in[13];
    const float* cw4 = (const float*)d_in[14];
    const float* cb4 = (const float*)d_in[15];
    const float* ga4 = (const float*)d_in[16];
    const float* be4 = (const float*)d_in[17];
    const float* W1  = (const float*)d_in[18];
    const float* b1  = (const float*)d_in[19];
    const float* W2  = (const float*)d_in[20];
    const float* b2  = (const float*)d_in[21];
    const float* W3  = (const float*)d_in[22];
    const float* b3  = (const float*)d_in[23];
    const float* W4  = (const float*)d_in[24];
    const float* b4  = (const float*)d_in[25];
    const float* F1  = (const float*)d_in[26];
    const float* fb1 = (const float*)d_in[27];
    const float* F2  = (const float*)d_in[28];
    const float* fb2 = (const float*)d_in[29];
    float* out = (float*)d_out;

    cudaFuncSetAttribute(conv_v3<E_, true >,
                         cudaFuncAttributeMaxDynamicSharedMemorySize, CSMEM3);
    cudaFuncSetAttribute(conv_v3<F_, false>,
                         cudaFuncAttributeMaxDynamicSharedMemorySize, CSMEM3);
    cudaFuncSetAttribute(pairwise_mma,
                         cudaFuncAttributeMaxDynamicSharedMemorySize, SMEM_PW);

    dim3 cgrid(RTILE, 4);

    // 0: one-time conv weight pack
    pack_conv<<<(CWP_TOTAL + 255) / 256, 256>>>(cw1, cw2, cw3, cw4);

    // 1..4: conv stack (smem activation tile, 2 blocks/SM)
    conv_v3<E_, true ><<<cgrid, 256, CSMEM3>>>(x, 0, 0, nullptr, nullptr, CB0, cb1, 0, 0);
    conv_v3<F_, false><<<cgrid, 256, CSMEM3>>>(nullptr, 0, 0, ga1, be1, CB1, cb2, 1, 1);
    conv_v3<F_, false><<<cgrid, 256, CSMEM3>>>(nullptr, 1, 1, ga2, be2, CB2, cb3, 0, 2);
    conv_v3<F_, false><<<cgrid, 256, CSMEM3>>>(nullptr, 0, 2, ga3, be3, CB3, cb4, 1, 3);

    // 5: projections (fused hb + layer-4 affine + pairwise weight packing)
    ac_kernel<<<dim3(B_, 6), 256>>>(W1, b1, h, ga4, be4, W2, W3, W4);

    // 6: persistent tensor-core pairwise chain
    pairwise_mma<<<PW_GRID, 256, SMEM_PW>>>(b2, b3, b4);

    // 7: decoder
    final_kernel<<<B_, 128>>>(F1, fb1, F2, fb2, out);
}